// round 14
// baseline (speedup 1.0000x reference)
#include <cuda_runtime.h>
#include <cuda_bf16.h>
#include <math.h>
#include <float.h>
#include <limits.h>
#include <stdint.h>

// ---------------- problem constants (fixed shapes) ----------------
#define NROWS 6272      // embedding rows
#define MROWS 32768     // memory bank rows
#define DDIM  128
#define BATCH 8
#define PPB   784
#define WIO   28
#define OUTSZ 224
#define KNEIGH 9
#define KSIZE 33
#define KRAD  16

#define NSPLIT 9
#define BNR 128                 // emb rows per CTA
#define BMC 64                  // mb cols per tile step
#define NTILES (MROWS / BMC)    // 512
#define LDTB 272                // smem tile row stride bytes (136 bf16)
#define TILE_A (128 * LDTB)     // 34816
#define TILE_B (64 * LDTB)      // 17408

// k_dist smem byte offsets
#define OFF_A     0
#define OFF_B0    (OFF_A + TILE_A)
#define OFF_B1    (OFF_B0 + TILE_B)
#define OFF_Y2    (OFF_B1 + TILE_B)            // 2 x 64 floats (halved y2)
#define OFF_RED   (OFF_Y2 + 512)               // 128*2 floats
#define SMEM_TOTAL (OFF_RED + 1024)            // 71680 bytes -> 3 CTAs/SM

// k_map smem layout
#define MAP_PM    0
#define MAP_GS    3136
#define MAP_UP    3280
#define MAP_VT    (MAP_UP + 48*224*4)
#define MAP_SMEM  (MAP_VT + 16*224*4)          // 60624 bytes

#define NDNN 9216                              // per-image dnn top9 partials

// ---------------- device scratch ----------------
__device__ float g_y2[MROWS];
__device__ float g_y2h[MROWS];
__device__ float g_x2[NROWS];
__device__ float g_pval[NSPLIT * NROWS];
__device__ float g_pscore[NROWS];
__device__ int   g_qrow[BATCH];
__device__ unsigned long long g_nnkey[BATCH]; // packed (ordered d2-q2 | idx)
__device__ int   g_done[BATCH];
__device__ float g_d9v[BATCH * NDNN];         // d^2 partials
__device__ int   g_d9i[BATCH * NDNN];
__device__ float g_gauss[KSIZE];
__device__ __nv_bfloat16 g_embh[NROWS * DDIM];
__device__ __nv_bfloat16 g_mbh[MROWS * DDIM];

// ---------------- small helpers ----------------
__device__ __forceinline__ uint32_t smem_u32(const void* p) {
    uint32_t a;
    asm("{ .reg .u64 t; cvta.to.shared.u64 t, %1; cvt.u32.u64 %0, t; }" : "=r"(a) : "l"(p));
    return a;
}
__device__ __forceinline__ void cp_async16(uint32_t dst, const void* src) {
    asm volatile("cp.async.cg.shared.global [%0], [%1], 16;" :: "r"(dst), "l"(src));
}
#define CP_COMMIT() asm volatile("cp.async.commit_group;" ::: "memory")
#define CP_WAIT0()  asm volatile("cp.async.wait_group 0;" ::: "memory")

__device__ __forceinline__ void ldm_x4(uint32_t addr, uint32_t& r0, uint32_t& r1,
                                       uint32_t& r2, uint32_t& r3) {
    asm volatile("ldmatrix.sync.aligned.m8n8.x4.shared.b16 {%0,%1,%2,%3}, [%4];"
                 : "=r"(r0), "=r"(r1), "=r"(r2), "=r"(r3) : "r"(addr));
}
__device__ __forceinline__ void mma16816(float* c, const uint32_t* a, const uint32_t* b) {
    asm volatile("mma.sync.aligned.m16n8k16.row.col.f32.bf16.bf16.f32 "
                 "{%0,%1,%2,%3}, {%4,%5,%6,%7}, {%8,%9}, {%0,%1,%2,%3};"
                 : "+f"(c[0]), "+f"(c[1]), "+f"(c[2]), "+f"(c[3])
                 : "r"(a[0]), "r"(a[1]), "r"(a[2]), "r"(a[3]), "r"(b[0]), "r"(b[1]));
}
__device__ __forceinline__ uint32_t f2ord(float f) {
    uint32_t u = __float_as_uint(f);
    return (u & 0x80000000u) ? ~u : (u | 0x80000000u);
}
__device__ __forceinline__ float ord2f(uint32_t u) {
    uint32_t b = (u & 0x80000000u) ? (u & 0x7FFFFFFFu) : ~u;
    return __uint_as_float(b);
}

// ---------------- k_prep: gauss + y2 + x2 + bf16 split ----------------
__global__ void k_prep(const float* __restrict__ emb, const float* __restrict__ mb) {
    if (blockIdx.x == 0 && threadIdx.x == 0) {
        float tmp[KSIZE]; float s = 0.0f;
        for (int i = 0; i < KSIZE; i++) {
            float x = (float)i - (float)(KSIZE - 1) * 0.5f;
            float t = x / 4.0f;
            tmp[i] = expf(-0.5f * t * t); s += tmp[i];
        }
        for (int i = 0; i < KSIZE; i++) g_gauss[i] = tmp[i] / s;
    }
    const int warp = threadIdx.x >> 5, lane = threadIdx.x & 31;
    const int r = lane >> 3, c = lane & 7;
    const int grow = blockIdx.x * 32 + warp * 4 + r;
    const float4* src4;
    uint2* dst2;
    int row;
    bool is_mb = (grow < MROWS);
    if (is_mb) { src4 = reinterpret_cast<const float4*>(mb); dst2 = reinterpret_cast<uint2*>(g_mbh); row = grow; }
    else       { src4 = reinterpret_cast<const float4*>(emb); dst2 = reinterpret_cast<uint2*>(g_embh); row = grow - MROWS; }

    float s = 0.0f;
    #pragma unroll
    for (int k = 0; k < 4; k++) {
        int idx = row * 32 + k * 8 + c;
        float4 v = src4[idx];
        s += v.x * v.x + v.y * v.y + v.z * v.z + v.w * v.w;
        __nv_bfloat162 h0, h1;
        h0.x = __float2bfloat16_rn(v.x); h0.y = __float2bfloat16_rn(v.y);
        h1.x = __float2bfloat16_rn(v.z); h1.y = __float2bfloat16_rn(v.w);
        uint2 p;
        p.x = *reinterpret_cast<uint32_t*>(&h0);
        p.y = *reinterpret_cast<uint32_t*>(&h1);
        dst2[idx] = p;
    }
    #pragma unroll
    for (int o = 1; o <= 4; o <<= 1) s += __shfl_xor_sync(0xFFFFFFFF, s, o);
    if (c == 0) {
        if (is_mb) { g_y2[row] = s; g_y2h[row] = 0.5f * s; }
        else       { g_x2[row] = s; }
    }
}

// ---------------- mma.sync fused distance GEMM (K=128, bf16-hi) + max ----------------
extern __shared__ char s_raw[];

__device__ __forceinline__ void load_tileA_async(uint32_t sm_dst,
                                                 const __nv_bfloat16* __restrict__ src,
                                                 int row0, int tid) {
    #pragma unroll
    for (int k = 0; k < 16; k++) {
        int i = k * 128 + tid;
        int r = i >> 4, c = i & 15;
        cp_async16(sm_dst + (uint32_t)(r * LDTB + c * 16),
                   (const char*)(src + (size_t)(row0 + r) * DDIM) + c * 16);
    }
}
__device__ __forceinline__ void load_tileB_async(uint32_t sm_dst,
                                                 const __nv_bfloat16* __restrict__ src,
                                                 int row0, int tid) {
    #pragma unroll
    for (int k = 0; k < 8; k++) {
        int i = k * 128 + tid;
        int r = i >> 4, c = i & 15;
        cp_async16(sm_dst + (uint32_t)(r * LDTB + c * 16),
                   (const char*)(src + (size_t)(row0 + r) * DDIM) + c * 16);
    }
}

__global__ void __launch_bounds__(128, 3) k_dist_mma() {
    char* smem = s_raw;
    const uint32_t sbase = smem_u32(smem);
    const int tid = threadIdx.x;
    const int wid = tid >> 5;
    const int lane = tid & 31;
    const int wm = wid & 1;
    const int wn = wid >> 1;
    const int rowBase = blockIdx.x * BNR;

    const int tile0 = (blockIdx.y * NTILES) / NSPLIT;
    const int tile1 = ((blockIdx.y + 1) * NTILES) / NSPLIT;

    const uint32_t A = sbase + OFF_A;
    const uint32_t B[2] = { sbase + OFF_B0, sbase + OFF_B1 };
    float* y2s = reinterpret_cast<float*>(smem + OFF_Y2);

    const int a_row = lane & 15;
    const int a_koff = (lane >> 4) << 3;
    const uint32_t aOff = (uint32_t)((wm * 64 + a_row) * LDTB + a_koff * 2);
    const int b_n = (lane & 7) + ((lane >> 4) << 3);
    const int b_koff = ((lane >> 3) & 1) << 3;
    const uint32_t bOff = (uint32_t)((wn * 32 + b_n) * LDTB + b_koff * 2);

    load_tileA_async(A, g_embh, rowBase, tid);
    load_tileB_async(B[0], g_mbh, tile0 * BMC, tid);
    if (tid < 16)
        cp_async16(sbase + OFF_Y2 + tid * 16, (const char*)(g_y2h + tile0 * BMC) + tid * 16);
    CP_COMMIT();
    CP_WAIT0();
    __syncthreads();

    float bestV[8];
    #pragma unroll
    for (int i = 0; i < 8; i++) bestV[i] = -FLT_MAX;

    for (int t = tile0; t < tile1; t++) {
        const int buf = (t - tile0) & 1;

        if (t + 1 < tile1) {
            const int nb = buf ^ 1;
            load_tileB_async(B[nb], g_mbh, (t + 1) * BMC, tid);
            if (tid < 16)
                cp_async16(sbase + OFF_Y2 + (uint32_t)(nb * 256 + tid * 16),
                           (const char*)(g_y2h + (size_t)(t + 1) * BMC) + tid * 16);
            CP_COMMIT();
        }

        float acc[4][4][4];
        #pragma unroll
        for (int mf = 0; mf < 4; mf++)
            #pragma unroll
            for (int nf = 0; nf < 4; nf++)
                #pragma unroll
                for (int r = 0; r < 4; r++) acc[mf][nf][r] = 0.0f;

        const uint32_t aB = A + aOff;
        const uint32_t bB = B[buf] + bOff;
        #pragma unroll
        for (int kc = 0; kc < 8; kc++) {
            const uint32_t kByte = (uint32_t)(kc << 5);
            uint32_t af[4][4];
            #pragma unroll
            for (int mf = 0; mf < 4; mf++)
                ldm_x4(aB + (uint32_t)(mf * 16 * LDTB) + kByte,
                       af[mf][0], af[mf][1], af[mf][2], af[mf][3]);
            uint32_t bf[4][2];
            #pragma unroll
            for (int q = 0; q < 2; q++) {
                uint32_t r0, r1, r2, r3;
                ldm_x4(bB + (uint32_t)(q * 16 * LDTB) + kByte, r0, r1, r2, r3);
                bf[q * 2][0] = r0; bf[q * 2][1] = r1;
                bf[q * 2 + 1][0] = r2; bf[q * 2 + 1][1] = r3;
            }
            #pragma unroll
            for (int mf = 0; mf < 4; mf++)
                #pragma unroll
                for (int nf = 0; nf < 4; nf++)
                    mma16816(acc[mf][nf], af[mf], bf[nf]);
        }

        {
            const float2* hy2 = reinterpret_cast<const float2*>(y2s + buf * 64);
            float2 hv[4];
            #pragma unroll
            for (int nf = 0; nf < 4; nf++)
                hv[nf] = hy2[(wn * 32 + nf * 8 + (lane & 3) * 2) >> 1];
            #pragma unroll
            for (int mf = 0; mf < 4; mf++) {
                #pragma unroll
                for (int h = 0; h < 2; h++) {
                    const int slot = mf * 2 + h;
                    float bv = bestV[slot];
                    #pragma unroll
                    for (int nf = 0; nf < 4; nf++) {
                        float s0 = acc[mf][nf][h * 2] - hv[nf].x;
                        float s1 = acc[mf][nf][h * 2 + 1] - hv[nf].y;
                        bv = fmaxf(bv, fmaxf(s0, s1));
                    }
                    bestV[slot] = bv;
                }
            }
        }

        if (t + 1 < tile1) CP_WAIT0();
        __syncthreads();
    }

    float* redV = reinterpret_cast<float*>(smem + OFF_RED);
    #pragma unroll
    for (int slot = 0; slot < 8; slot++) {
        float v = bestV[slot];
        v = fmaxf(v, __shfl_xor_sync(0xFFFFFFFF, v, 1));
        v = fmaxf(v, __shfl_xor_sync(0xFFFFFFFF, v, 2));
        if ((lane & 3) == 0) {
            int mf = slot >> 1, h = slot & 1;
            int row = wm * 64 + mf * 16 + (lane >> 2) + h * 8;
            redV[row * 2 + wn] = v;
        }
    }
    __syncthreads();
    if (tid < BNR) {
        float bv = fmaxf(redV[tid * 2], redV[tid * 2 + 1]);
        g_pval[blockIdx.y * NROWS + rowBase + tid] = bv;
    }
}

// ---------------- fused: patch scores + per-image argmax (+reset keys) ----------------
__global__ void k_score() {
    int b = blockIdx.x, tid = threadIdx.x;
    __shared__ float sv[256]; __shared__ int si[256];
    if (tid == 0) { g_nnkey[b] = 0xFFFFFFFFFFFFFFFFull; g_done[b] = 0; }
    float bmax = -FLT_MAX; int bi = INT_MAX;
    for (int p = tid; p < PPB; p += 256) {
        int row = b * PPB + p;
        float bv = -FLT_MAX;
        #pragma unroll
        for (int s = 0; s < NSPLIT; s++) bv = fmaxf(bv, g_pval[s * NROWS + row]);
        float d2 = g_x2[row] - 2.0f * bv;
        float sc = sqrtf(fmaxf(d2, 0.0f));
        g_pscore[row] = sc;
        if (sc > bmax || (sc == bmax && p < bi)) { bmax = sc; bi = p; }
    }
    sv[tid] = bmax; si[tid] = bi;
    __syncthreads();
    for (int s = 128; s > 0; s >>= 1) {
        if (tid < s) {
            if (sv[tid + s] > sv[tid] || (sv[tid + s] == sv[tid] && si[tid + s] < si[tid])) {
                sv[tid] = sv[tid + s]; si[tid] = si[tid + s];
            }
        }
        __syncthreads();
    }
    if (tid == 0) g_qrow[b] = b * PPB + si[0];
}

// ---------------- exact fp32 argmin over mb, row-pair MLP, atomic-merged ----------------
// grid (128, 8), block 256 = 8 warps x 32 rows
__global__ void k_qpart(const float* __restrict__ emb, const float* __restrict__ mb) {
    const int b = blockIdx.y;
    const int warp = threadIdx.x >> 5, lane = threadIdx.x & 31;
    const int r = lane >> 3, c = lane & 7;
    const float4* mb4 = reinterpret_cast<const float4*>(mb);
    const float4* q4p = reinterpret_cast<const float4*>(emb + (size_t)g_qrow[b] * DDIM);

    float4 q4[4];
    #pragma unroll
    for (int k = 0; k < 4; k++) q4[k] = q4p[k * 8 + c];

    float bv = FLT_MAX; int bi = INT_MAX;
    const int base = blockIdx.x * 256 + warp * 32;
    #pragma unroll
    for (int g = 0; g < 8; g += 2) {
        int row0 = base + g * 4 + r;
        int row1 = row0 + 4;
        float4 m0[4], m1[4];
        #pragma unroll
        for (int k = 0; k < 4; k++) m0[k] = mb4[row0 * 32 + k * 8 + c];
        #pragma unroll
        for (int k = 0; k < 4; k++) m1[k] = mb4[row1 * 32 + k * 8 + c];
        float d0 = 0.0f, d1 = 0.0f;
        #pragma unroll
        for (int k = 0; k < 4; k++) {
            d0 += q4[k].x * m0[k].x + q4[k].y * m0[k].y + q4[k].z * m0[k].z + q4[k].w * m0[k].w;
            d1 += q4[k].x * m1[k].x + q4[k].y * m1[k].y + q4[k].z * m1[k].z + q4[k].w * m1[k].w;
        }
        #pragma unroll
        for (int o = 1; o <= 4; o <<= 1) {
            d0 += __shfl_xor_sync(0xFFFFFFFF, d0, o);
            d1 += __shfl_xor_sync(0xFFFFFFFF, d1, o);
        }
        float e0 = g_y2[row0] - 2.0f * d0;
        float e1 = g_y2[row1] - 2.0f * d1;
        if (e0 < bv) { bv = e0; bi = row0; }
        if (e1 < bv) { bv = e1; bi = row1; }
    }
    #pragma unroll
    for (int o = 8; o <= 16; o <<= 1) {
        float ov = __shfl_xor_sync(0xFFFFFFFF, bv, o);
        int oi = __shfl_xor_sync(0xFFFFFFFF, bi, o);
        if (ov < bv || (ov == bv && oi < bi)) { bv = ov; bi = oi; }
    }
    __shared__ float sv[8]; __shared__ int si[8];
    if (lane == 0) { sv[warp] = bv; si[warp] = bi; }
    __syncthreads();
    if (threadIdx.x == 0) {
        float v = sv[0]; int ix = si[0];
        for (int w = 1; w < 8; w++)
            if (sv[w] < v || (sv[w] == v && si[w] < ix)) { v = sv[w]; ix = si[w]; }
        unsigned long long key = ((unsigned long long)f2ord(v) << 32) | (unsigned)ix;
        atomicMin(&g_nnkey[b], key);
    }
}

// ---------------- dnn d^2 top-9 partials + last-block final merge ----------------
// grid (128, 8), block 256 = 8 warps x 32 rows
__global__ void k_dnn9(const float* __restrict__ emb, const float* __restrict__ mb,
                       float* __restrict__ out) {
    const int b = blockIdx.y;
    const int warp = threadIdx.x >> 5, lane = threadIdx.x & 31;
    const int r = lane >> 3, c = lane & 7;
    const int nn = (int)(g_nnkey[b] & 0xFFFFFFFFull);
    const float4* mb4 = reinterpret_cast<const float4*>(mb);
    const float4* q4p = reinterpret_cast<const float4*>(mb + (size_t)nn * DDIM);
    const float y2q = g_y2[nn];

    float4 q4[4];
    #pragma unroll
    for (int k = 0; k < 4; k++) q4[k] = q4p[k * 8 + c];

    float tv[KNEIGH]; int ti9[KNEIGH];
    #pragma unroll
    for (int j = 0; j < KNEIGH; j++) { tv[j] = FLT_MAX; ti9[j] = INT_MAX; }

    const int base = blockIdx.x * 256 + warp * 32;
    #pragma unroll
    for (int g = 0; g < 8; g += 2) {
        int row0 = base + g * 4 + r;
        int row1 = row0 + 4;
        float4 m0[4], m1[4];
        #pragma unroll
        for (int k = 0; k < 4; k++) m0[k] = mb4[row0 * 32 + k * 8 + c];
        #pragma unroll
        for (int k = 0; k < 4; k++) m1[k] = mb4[row1 * 32 + k * 8 + c];
        float d0 = 0.0f, d1 = 0.0f;
        #pragma unroll
        for (int k = 0; k < 4; k++) {
            d0 += q4[k].x * m0[k].x + q4[k].y * m0[k].y + q4[k].z * m0[k].z + q4[k].w * m0[k].w;
            d1 += q4[k].x * m1[k].x + q4[k].y * m1[k].y + q4[k].z * m1[k].z + q4[k].w * m1[k].w;
        }
        #pragma unroll
        for (int o = 1; o <= 4; o <<= 1) {
            d0 += __shfl_xor_sync(0xFFFFFFFF, d0, o);
            d1 += __shfl_xor_sync(0xFFFFFFFF, d1, o);
        }
        float e0 = y2q - 2.0f * d0 + g_y2[row0];
        float e1 = y2q - 2.0f * d1 + g_y2[row1];
        // lane0 gathers the 8 row results (2 per group of lanes r=0..3)
        #pragma unroll
        for (int rr = 0; rr < 4; rr++) {
            float v0 = __shfl_sync(0xFFFFFFFF, e0, rr * 8);
            float v1 = __shfl_sync(0xFFFFFFFF, e1, rr * 8);
            if (lane == 0) {
                int rowa = base + g * 4 + rr;
                int rowb = rowa + 4;
                if (v0 < tv[KNEIGH - 1] || (v0 == tv[KNEIGH - 1] && rowa < ti9[KNEIGH - 1])) {
                    int pos = KNEIGH - 1;
                    while (pos > 0 && (v0 < tv[pos - 1] || (v0 == tv[pos - 1] && rowa < ti9[pos - 1]))) {
                        tv[pos] = tv[pos - 1]; ti9[pos] = ti9[pos - 1]; pos--;
                    }
                    tv[pos] = v0; ti9[pos] = rowa;
                }
                if (v1 < tv[KNEIGH - 1] || (v1 == tv[KNEIGH - 1] && rowb < ti9[KNEIGH - 1])) {
                    int pos = KNEIGH - 1;
                    while (pos > 0 && (v1 < tv[pos - 1] || (v1 == tv[pos - 1] && rowb < ti9[pos - 1]))) {
                        tv[pos] = tv[pos - 1]; ti9[pos] = ti9[pos - 1]; pos--;
                    }
                    tv[pos] = v1; ti9[pos] = rowb;
                }
            }
        }
    }
    if (lane == 0) {
        int off = b * NDNN + (blockIdx.x * 8 + warp) * KNEIGH;
        #pragma unroll
        for (int j = 0; j < KNEIGH; j++) { g_d9v[off + j] = tv[j]; g_d9i[off + j] = ti9[j]; }
    }
    __syncthreads();

    // ---- last block for image b does the final merge + softmax + out[b] ----
    __shared__ int s_last;
    if (threadIdx.x == 0) {
        __threadfence();
        s_last = atomicAdd(&g_done[b], 1);
    }
    __syncthreads();
    if (s_last != gridDim.x - 1) return;

    const int tid = threadIdx.x;
    __shared__ float hv[256]; __shared__ int hidx[256]; __shared__ int hthr[256];
    __shared__ int sel[KNEIGH]; __shared__ float dists[KNEIGH];

    float mv[KNEIGH]; int mi[KNEIGH];
    #pragma unroll
    for (int j = 0; j < KNEIGH; j++) { mv[j] = FLT_MAX; mi[j] = INT_MAX; }
    for (int m = tid; m < NDNN; m += 256) {
        float v = g_d9v[b * NDNN + m];
        int ix = g_d9i[b * NDNN + m];
        if (v < mv[KNEIGH - 1] || (v == mv[KNEIGH - 1] && ix < mi[KNEIGH - 1])) {
            int pos = KNEIGH - 1;
            while (pos > 0 && (v < mv[pos - 1] || (v == mv[pos - 1] && ix < mi[pos - 1]))) {
                mv[pos] = mv[pos - 1]; mi[pos] = mi[pos - 1]; pos--;
            }
            mv[pos] = v; mi[pos] = ix;
        }
    }
    int cur = 0;
    for (int it = 0; it < KNEIGH; it++) {
        hv[tid] = (cur < KNEIGH) ? mv[cur] : FLT_MAX;
        hidx[tid] = (cur < KNEIGH) ? mi[cur] : INT_MAX;
        hthr[tid] = tid;
        __syncthreads();
        for (int s = 128; s > 0; s >>= 1) {
            if (tid < s) {
                if (hv[tid + s] < hv[tid] ||
                    (hv[tid + s] == hv[tid] && hidx[tid + s] < hidx[tid])) {
                    hv[tid] = hv[tid + s]; hidx[tid] = hidx[tid + s]; hthr[tid] = hthr[tid + s];
                }
            }
            __syncthreads();
        }
        if (tid == 0) sel[it] = hidx[0];
        int win = hthr[0];
        __syncthreads();
        if (tid == win) cur++;
    }

    if (tid < KNEIGH) {
        const float* q = emb + (size_t)g_qrow[b] * DDIM;
        const float* m = mb + (size_t)sel[tid] * DDIM;
        float dot = 0.0f, q2 = 0.0f;
        #pragma unroll 4
        for (int d = 0; d < DDIM; d++) { dot += q[d] * m[d]; q2 += q[d] * q[d]; }
        float d2 = q2 - 2.0f * dot + g_y2[sel[tid]];
        dists[tid] = sqrtf(fmaxf(d2, 0.0f));
    }
    __syncthreads();
    if (tid == 0) {
        float mx = dists[0];
        for (int j = 1; j < KNEIGH; j++) mx = fmaxf(mx, dists[j]);
        float sum = 0.0f, e0 = 0.0f;
        for (int j = 0; j < KNEIGH; j++) {
            float e = expf(dists[j] - mx);
            if (j == 0) e0 = e;
            sum += e;
        }
        float d2m = ord2f((uint32_t)(g_nnkey[b] >> 32));
        float score = sqrtf(fmaxf(g_x2[g_qrow[b]] + d2m, 0.0f));
        out[b] = (1.0f - e0 / sum) * score;
    }
}

// ---------------- fused upsample + separable Gaussian blur ----------------
__global__ void k_map(float* __restrict__ out) {
    char* smem = s_raw;
    float* pm = reinterpret_cast<float*>(smem + MAP_PM);
    float* gs = reinterpret_cast<float*>(smem + MAP_GS);
    float* up = reinterpret_cast<float*>(smem + MAP_UP);
    float* vt = reinterpret_cast<float*>(smem + MAP_VT);
    const int band = blockIdx.x, b = blockIdx.y;
    const int tid = threadIdx.x;
    const int r0 = band * 16;

    for (int i = tid; i < PPB; i += 256) pm[i] = g_pscore[b * PPB + i];
    if (tid < KSIZE) gs[tid] = g_gauss[tid];
    __syncthreads();

    for (int i = tid; i < 48 * 224; i += 256) {
        int j = i / 224, V = i % 224;
        int U = r0 - 16 + j;
        if (U < 0) U = -U;
        if (U > OUTSZ - 1) U = 2 * (OUTSZ - 1) - U;
        float su = ((float)U + 0.5f) * 0.125f - 0.5f;
        float sv = ((float)V + 0.5f) * 0.125f - 0.5f;
        int u0 = (int)floorf(su), v0 = (int)floorf(sv);
        float tu = su - (float)u0, tvv = sv - (float)v0;
        int u0c = min(max(u0, 0), WIO - 1), u1c = min(max(u0 + 1, 0), WIO - 1);
        int v0c = min(max(v0, 0), WIO - 1), v1c = min(max(v0 + 1, 0), WIO - 1);
        float v00 = pm[u0c * WIO + v0c], v01 = pm[u0c * WIO + v1c];
        float v10 = pm[u1c * WIO + v0c], v11 = pm[u1c * WIO + v1c];
        float top = v00 + tvv * (v01 - v00);
        float bot = v10 + tvv * (v11 - v10);
        up[i] = top + tu * (bot - top);
    }
    __syncthreads();

    for (int i = tid; i < 16 * 224; i += 256) {
        int du = i / 224, V = i % 224;
        float acc = 0.0f;
        #pragma unroll
        for (int k = 0; k < KSIZE; k++) acc += gs[k] * up[(du + k) * 224 + V];
        vt[i] = acc;
    }
    __syncthreads();

    for (int i = tid; i < 16 * 224; i += 256) {
        int du = i / 224, V = i % 224;
        float acc = 0.0f;
        #pragma unroll
        for (int k = 0; k < KSIZE; k++) {
            int jv = V - KRAD + k;
            if (jv < 0) jv = -jv;
            if (jv > OUTSZ - 1) jv = 2 * (OUTSZ - 1) - jv;
            acc += gs[k] * vt[du * 224 + jv];
        }
        out[BATCH + (b * OUTSZ + r0 + du) * OUTSZ + V] = acc;
    }
}

// ---------------- launcher (fork-join: map branch || pred_score branch) ----------------
extern "C" void kernel_launch(void* const* d_in, const int* in_sizes, int n_in,
                              void* d_out, int out_size) {
    const float* emb = (const float*)d_in[0];
    const float* mb = (const float*)d_in[1];
    float* out = (float*)d_out;

    static bool init_done = false;
    static cudaStream_t s2;
    static cudaEvent_t evFork, evJoin;
    if (!init_done) {
        cudaFuncSetAttribute(k_dist_mma, cudaFuncAttributeMaxDynamicSharedMemorySize, SMEM_TOTAL);
        cudaFuncSetAttribute(k_map, cudaFuncAttributeMaxDynamicSharedMemorySize, MAP_SMEM);
        cudaStreamCreateWithFlags(&s2, cudaStreamNonBlocking);
        cudaEventCreateWithFlags(&evFork, cudaEventDisableTiming);
        cudaEventCreateWithFlags(&evJoin, cudaEventDisableTiming);
        init_done = true;
    }

    k_prep<<<(MROWS + NROWS) / 32, 256>>>(emb, mb);

    dim3 gdist(NROWS / BNR, NSPLIT);
    k_dist_mma<<<gdist, 128, SMEM_TOTAL>>>();

    k_score<<<BATCH, 256>>>();

    // fork: anomaly-map branch on s2 (depends only on g_pscore)
    cudaEventRecord(evFork, 0);
    cudaStreamWaitEvent(s2, evFork, 0);
    dim3 gmap(14, BATCH);
    k_map<<<gmap, 256, MAP_SMEM, s2>>>(out);
    cudaEventRecord(evJoin, s2);

    // main: pred_score branch
    dim3 gq(128, BATCH);
    k_qpart<<<gq, 256>>>(emb, mb);

    dim3 gd9(128, BATCH);
    k_dnn9<<<gd9, 256>>>(emb, mb, out);

    // join
    cudaStreamWaitEvent(0, evJoin, 0);
}

// round 16
// speedup vs baseline: 1.0605x; 1.0605x over previous
#include <cuda_runtime.h>
#include <cuda_bf16.h>
#include <math.h>
#include <float.h>
#include <limits.h>
#include <stdint.h>

// ---------------- problem constants (fixed shapes) ----------------
#define NROWS 6272      // embedding rows
#define MROWS 32768     // memory bank rows
#define DDIM  128
#define BATCH 8
#define PPB   784
#define WIO   28
#define OUTSZ 224
#define KNEIGH 9
#define KSIZE 33
#define KRAD  16

#define NSPLIT 9
#define BNR 128                 // emb rows per CTA
#define BMC 64                  // mb cols per tile step
#define NTILES (MROWS / BMC)    // 512
#define LDTB 272                // smem tile row stride bytes (136 bf16)
#define TILE_A (128 * LDTB)     // 34816
#define TILE_B (64 * LDTB)      // 17408

// k_dist smem byte offsets
#define OFF_A     0
#define OFF_B0    (OFF_A + TILE_A)
#define OFF_B1    (OFF_B0 + TILE_B)
#define OFF_Y2    (OFF_B1 + TILE_B)            // 2 x 64 floats (halved y2)
#define OFF_RED   (OFF_Y2 + 512)               // 128*2 floats
#define SMEM_TOTAL (OFF_RED + 1024)            // 71680 bytes -> 3 CTAs/SM

// k_map smem layout (8-row bands: 40 upsample rows + 8 vt rows)
#define MAP_BAND  8
#define MAP_UPR   (MAP_BAND + 2 * KRAD)        // 40
#define MAP_PM    0
#define MAP_GS    3136
#define MAP_UP    3280
#define MAP_VT    (MAP_UP + MAP_UPR*224*4)
#define MAP_SMEM  (MAP_VT + MAP_BAND*224*4)    // ~47 KB

#define NDNN 9216                              // per-image dnn top9 partials (128 blk * 8 warps * 9)

// ---------------- device scratch ----------------
__device__ float g_y2[MROWS];
__device__ float g_y2h[MROWS];
__device__ float g_x2[NROWS];
__device__ float g_pval[NSPLIT * NROWS];
__device__ float g_pscore[NROWS];
__device__ int   g_qrow[BATCH];
__device__ unsigned long long g_nnkey[BATCH]; // packed (ordered d2-q2 | idx)
__device__ int   g_done[BATCH];
__device__ float g_d9v[BATCH * NDNN];         // d^2 partials
__device__ int   g_d9i[BATCH * NDNN];
__device__ float g_gauss[KSIZE];
__device__ __nv_bfloat16 g_embh[NROWS * DDIM];
__device__ __nv_bfloat16 g_mbh[MROWS * DDIM];

// ---------------- small helpers ----------------
__device__ __forceinline__ uint32_t smem_u32(const void* p) {
    uint32_t a;
    asm("{ .reg .u64 t; cvta.to.shared.u64 t, %1; cvt.u32.u64 %0, t; }" : "=r"(a) : "l"(p));
    return a;
}
__device__ __forceinline__ void cp_async16(uint32_t dst, const void* src) {
    asm volatile("cp.async.cg.shared.global [%0], [%1], 16;" :: "r"(dst), "l"(src));
}
#define CP_COMMIT() asm volatile("cp.async.commit_group;" ::: "memory")
#define CP_WAIT0()  asm volatile("cp.async.wait_group 0;" ::: "memory")

__device__ __forceinline__ void ldm_x4(uint32_t addr, uint32_t& r0, uint32_t& r1,
                                       uint32_t& r2, uint32_t& r3) {
    asm volatile("ldmatrix.sync.aligned.m8n8.x4.shared.b16 {%0,%1,%2,%3}, [%4];"
                 : "=r"(r0), "=r"(r1), "=r"(r2), "=r"(r3) : "r"(addr));
}
__device__ __forceinline__ void mma16816(float* c, const uint32_t* a, const uint32_t* b) {
    asm volatile("mma.sync.aligned.m16n8k16.row.col.f32.bf16.bf16.f32 "
                 "{%0,%1,%2,%3}, {%4,%5,%6,%7}, {%8,%9}, {%0,%1,%2,%3};"
                 : "+f"(c[0]), "+f"(c[1]), "+f"(c[2]), "+f"(c[3])
                 : "r"(a[0]), "r"(a[1]), "r"(a[2]), "r"(a[3]), "r"(b[0]), "r"(b[1]));
}
__device__ __forceinline__ uint32_t f2ord(float f) {
    uint32_t u = __float_as_uint(f);
    return (u & 0x80000000u) ? ~u : (u | 0x80000000u);
}
__device__ __forceinline__ float ord2f(uint32_t u) {
    uint32_t b = (u & 0x80000000u) ? (u & 0x7FFFFFFFu) : ~u;
    return __uint_as_float(b);
}

// ---------------- k_prep: gauss + y2 + x2 + bf16 split ----------------
__global__ void k_prep(const float* __restrict__ emb, const float* __restrict__ mb) {
    if (blockIdx.x == 0 && threadIdx.x == 0) {
        float tmp[KSIZE]; float s = 0.0f;
        for (int i = 0; i < KSIZE; i++) {
            float x = (float)i - (float)(KSIZE - 1) * 0.5f;
            float t = x / 4.0f;
            tmp[i] = expf(-0.5f * t * t); s += tmp[i];
        }
        for (int i = 0; i < KSIZE; i++) g_gauss[i] = tmp[i] / s;
    }
    const int warp = threadIdx.x >> 5, lane = threadIdx.x & 31;
    const int r = lane >> 3, c = lane & 7;
    const int grow = blockIdx.x * 32 + warp * 4 + r;
    const float4* src4;
    uint2* dst2;
    int row;
    bool is_mb = (grow < MROWS);
    if (is_mb) { src4 = reinterpret_cast<const float4*>(mb); dst2 = reinterpret_cast<uint2*>(g_mbh); row = grow; }
    else       { src4 = reinterpret_cast<const float4*>(emb); dst2 = reinterpret_cast<uint2*>(g_embh); row = grow - MROWS; }

    float s = 0.0f;
    #pragma unroll
    for (int k = 0; k < 4; k++) {
        int idx = row * 32 + k * 8 + c;
        float4 v = src4[idx];
        s += v.x * v.x + v.y * v.y + v.z * v.z + v.w * v.w;
        __nv_bfloat162 h0, h1;
        h0.x = __float2bfloat16_rn(v.x); h0.y = __float2bfloat16_rn(v.y);
        h1.x = __float2bfloat16_rn(v.z); h1.y = __float2bfloat16_rn(v.w);
        uint2 p;
        p.x = *reinterpret_cast<uint32_t*>(&h0);
        p.y = *reinterpret_cast<uint32_t*>(&h1);
        dst2[idx] = p;
    }
    #pragma unroll
    for (int o = 1; o <= 4; o <<= 1) s += __shfl_xor_sync(0xFFFFFFFF, s, o);
    if (c == 0) {
        if (is_mb) { g_y2[row] = s; g_y2h[row] = 0.5f * s; }
        else       { g_x2[row] = s; }
    }
}

// ---------------- mma.sync fused distance GEMM (K=128, bf16-hi) + max ----------------
extern __shared__ char s_raw[];

__device__ __forceinline__ void load_tileA_async(uint32_t sm_dst,
                                                 const __nv_bfloat16* __restrict__ src,
                                                 int row0, int tid) {
    #pragma unroll
    for (int k = 0; k < 16; k++) {
        int i = k * 128 + tid;
        int r = i >> 4, c = i & 15;
        cp_async16(sm_dst + (uint32_t)(r * LDTB + c * 16),
                   (const char*)(src + (size_t)(row0 + r) * DDIM) + c * 16);
    }
}
__device__ __forceinline__ void load_tileB_async(uint32_t sm_dst,
                                                 const __nv_bfloat16* __restrict__ src,
                                                 int row0, int tid) {
    #pragma unroll
    for (int k = 0; k < 8; k++) {
        int i = k * 128 + tid;
        int r = i >> 4, c = i & 15;
        cp_async16(sm_dst + (uint32_t)(r * LDTB + c * 16),
                   (const char*)(src + (size_t)(row0 + r) * DDIM) + c * 16);
    }
}

__global__ void __launch_bounds__(128, 3) k_dist_mma() {
    char* smem = s_raw;
    const uint32_t sbase = smem_u32(smem);
    const int tid = threadIdx.x;
    const int wid = tid >> 5;
    const int lane = tid & 31;
    const int wm = wid & 1;
    const int wn = wid >> 1;
    const int rowBase = blockIdx.x * BNR;

    const int tile0 = (blockIdx.y * NTILES) / NSPLIT;
    const int tile1 = ((blockIdx.y + 1) * NTILES) / NSPLIT;

    const uint32_t A = sbase + OFF_A;
    const uint32_t B[2] = { sbase + OFF_B0, sbase + OFF_B1 };
    float* y2s = reinterpret_cast<float*>(smem + OFF_Y2);

    const int a_row = lane & 15;
    const int a_koff = (lane >> 4) << 3;
    const uint32_t aOff = (uint32_t)((wm * 64 + a_row) * LDTB + a_koff * 2);
    const int b_n = (lane & 7) + ((lane >> 4) << 3);
    const int b_koff = ((lane >> 3) & 1) << 3;
    const uint32_t bOff = (uint32_t)((wn * 32 + b_n) * LDTB + b_koff * 2);

    load_tileA_async(A, g_embh, rowBase, tid);
    load_tileB_async(B[0], g_mbh, tile0 * BMC, tid);
    if (tid < 16)
        cp_async16(sbase + OFF_Y2 + tid * 16, (const char*)(g_y2h + tile0 * BMC) + tid * 16);
    CP_COMMIT();
    CP_WAIT0();
    __syncthreads();

    float bestV[8];
    #pragma unroll
    for (int i = 0; i < 8; i++) bestV[i] = -FLT_MAX;

    for (int t = tile0; t < tile1; t++) {
        const int buf = (t - tile0) & 1;

        if (t + 1 < tile1) {
            const int nb = buf ^ 1;
            load_tileB_async(B[nb], g_mbh, (t + 1) * BMC, tid);
            if (tid < 16)
                cp_async16(sbase + OFF_Y2 + (uint32_t)(nb * 256 + tid * 16),
                           (const char*)(g_y2h + (size_t)(t + 1) * BMC) + tid * 16);
            CP_COMMIT();
        }

        float acc[4][4][4];
        #pragma unroll
        for (int mf = 0; mf < 4; mf++)
            #pragma unroll
            for (int nf = 0; nf < 4; nf++)
                #pragma unroll
                for (int r = 0; r < 4; r++) acc[mf][nf][r] = 0.0f;

        const uint32_t aB = A + aOff;
        const uint32_t bB = B[buf] + bOff;
        #pragma unroll
        for (int kc = 0; kc < 8; kc++) {
            const uint32_t kByte = (uint32_t)(kc << 5);
            uint32_t af[4][4];
            #pragma unroll
            for (int mf = 0; mf < 4; mf++)
                ldm_x4(aB + (uint32_t)(mf * 16 * LDTB) + kByte,
                       af[mf][0], af[mf][1], af[mf][2], af[mf][3]);
            uint32_t bf[4][2];
            #pragma unroll
            for (int q = 0; q < 2; q++) {
                uint32_t r0, r1, r2, r3;
                ldm_x4(bB + (uint32_t)(q * 16 * LDTB) + kByte, r0, r1, r2, r3);
                bf[q * 2][0] = r0; bf[q * 2][1] = r1;
                bf[q * 2 + 1][0] = r2; bf[q * 2 + 1][1] = r3;
            }
            #pragma unroll
            for (int mf = 0; mf < 4; mf++)
                #pragma unroll
                for (int nf = 0; nf < 4; nf++)
                    mma16816(acc[mf][nf], af[mf], bf[nf]);
        }

        {
            const float2* hy2 = reinterpret_cast<const float2*>(y2s + buf * 64);
            float2 hv[4];
            #pragma unroll
            for (int nf = 0; nf < 4; nf++)
                hv[nf] = hy2[(wn * 32 + nf * 8 + (lane & 3) * 2) >> 1];
            #pragma unroll
            for (int mf = 0; mf < 4; mf++) {
                #pragma unroll
                for (int h = 0; h < 2; h++) {
                    const int slot = mf * 2 + h;
                    float bv = bestV[slot];
                    #pragma unroll
                    for (int nf = 0; nf < 4; nf++) {
                        float s0 = acc[mf][nf][h * 2] - hv[nf].x;
                        float s1 = acc[mf][nf][h * 2 + 1] - hv[nf].y;
                        bv = fmaxf(bv, fmaxf(s0, s1));
                    }
                    bestV[slot] = bv;
                }
            }
        }

        if (t + 1 < tile1) CP_WAIT0();
        __syncthreads();
    }

    float* redV = reinterpret_cast<float*>(smem + OFF_RED);
    #pragma unroll
    for (int slot = 0; slot < 8; slot++) {
        float v = bestV[slot];
        v = fmaxf(v, __shfl_xor_sync(0xFFFFFFFF, v, 1));
        v = fmaxf(v, __shfl_xor_sync(0xFFFFFFFF, v, 2));
        if ((lane & 3) == 0) {
            int mf = slot >> 1, h = slot & 1;
            int row = wm * 64 + mf * 16 + (lane >> 2) + h * 8;
            redV[row * 2 + wn] = v;
        }
    }
    __syncthreads();
    if (tid < BNR) {
        float bv = fmaxf(redV[tid * 2], redV[tid * 2 + 1]);
        g_pval[blockIdx.y * NROWS + rowBase + tid] = bv;
    }
}

// ---------------- fused: patch scores + per-image argmax (+reset keys) ----------------
__global__ void k_score() {
    int b = blockIdx.x, tid = threadIdx.x;
    __shared__ float sv[256]; __shared__ int si[256];
    if (tid == 0) { g_nnkey[b] = 0xFFFFFFFFFFFFFFFFull; g_done[b] = 0; }
    float bmax = -FLT_MAX; int bi = INT_MAX;
    for (int p = tid; p < PPB; p += 256) {
        int row = b * PPB + p;
        float bv = -FLT_MAX;
        #pragma unroll
        for (int s = 0; s < NSPLIT; s++) bv = fmaxf(bv, g_pval[s * NROWS + row]);
        float d2 = g_x2[row] - 2.0f * bv;
        float sc = sqrtf(fmaxf(d2, 0.0f));
        g_pscore[row] = sc;
        if (sc > bmax || (sc == bmax && p < bi)) { bmax = sc; bi = p; }
    }
    sv[tid] = bmax; si[tid] = bi;
    __syncthreads();
    for (int s = 128; s > 0; s >>= 1) {
        if (tid < s) {
            if (sv[tid + s] > sv[tid] || (sv[tid + s] == sv[tid] && si[tid + s] < si[tid])) {
                sv[tid] = sv[tid + s]; si[tid] = si[tid + s];
            }
        }
        __syncthreads();
    }
    if (tid == 0) g_qrow[b] = b * PPB + si[0];
}

// ---------------- exact fp32 argmin over mb, 4-rows-per-warp, atomic-merged ----------------
// grid (128, 8), block 256 = 8 warps x 32 rows
__global__ void k_qpart(const float* __restrict__ emb, const float* __restrict__ mb) {
    const int b = blockIdx.y;
    const int warp = threadIdx.x >> 5, lane = threadIdx.x & 31;
    const int r = lane >> 3, c = lane & 7;
    const float4* mb4 = reinterpret_cast<const float4*>(mb);
    const float4* q4p = reinterpret_cast<const float4*>(emb + (size_t)g_qrow[b] * DDIM);

    float4 q4[4];
    #pragma unroll
    for (int k = 0; k < 4; k++) q4[k] = q4p[k * 8 + c];

    float bv = FLT_MAX; int bi = INT_MAX;
    const int base = blockIdx.x * 256 + warp * 32;
    #pragma unroll
    for (int g = 0; g < 8; g++) {
        int row = base + g * 4 + r;
        float dot = 0.0f;
        #pragma unroll
        for (int k = 0; k < 4; k++) {
            float4 m = mb4[row * 32 + k * 8 + c];
            dot += q4[k].x * m.x + q4[k].y * m.y + q4[k].z * m.z + q4[k].w * m.w;
        }
        #pragma unroll
        for (int o = 1; o <= 4; o <<= 1) dot += __shfl_xor_sync(0xFFFFFFFF, dot, o);
        float d2 = g_y2[row] - 2.0f * dot;      // +q^2 constant: argmin-invariant
        if (d2 < bv) { bv = d2; bi = row; }
    }
    #pragma unroll
    for (int o = 8; o <= 16; o <<= 1) {
        float ov = __shfl_xor_sync(0xFFFFFFFF, bv, o);
        int oi = __shfl_xor_sync(0xFFFFFFFF, bi, o);
        if (ov < bv || (ov == bv && oi < bi)) { bv = ov; bi = oi; }
    }
    __shared__ float sv[8]; __shared__ int si[8];
    if (lane == 0) { sv[warp] = bv; si[warp] = bi; }
    __syncthreads();
    if (threadIdx.x == 0) {
        float v = sv[0]; int ix = si[0];
        for (int w = 1; w < 8; w++)
            if (sv[w] < v || (sv[w] == v && si[w] < ix)) { v = sv[w]; ix = si[w]; }
        unsigned long long key = ((unsigned long long)f2ord(v) << 32) | (unsigned)ix;
        atomicMin(&g_nnkey[b], key);
    }
}

// ---------------- dnn d^2 top-9 partials + last-block final merge ----------------
// grid (128, 8), block 256 = 8 warps x 32 rows
__global__ void k_dnn9(const float* __restrict__ emb, const float* __restrict__ mb,
                       float* __restrict__ out) {
    const int b = blockIdx.y;
    const int warp = threadIdx.x >> 5, lane = threadIdx.x & 31;
    const int r = lane >> 3, c = lane & 7;
    const int nn = (int)(g_nnkey[b] & 0xFFFFFFFFull);
    const float4* mb4 = reinterpret_cast<const float4*>(mb);
    const float4* q4p = reinterpret_cast<const float4*>(mb + (size_t)nn * DDIM);
    const float y2q = g_y2[nn];

    float4 q4[4];
    #pragma unroll
    for (int k = 0; k < 4; k++) q4[k] = q4p[k * 8 + c];

    float tv[KNEIGH]; int ti9[KNEIGH];
    #pragma unroll
    for (int j = 0; j < KNEIGH; j++) { tv[j] = FLT_MAX; ti9[j] = INT_MAX; }

    const int base = blockIdx.x * 256 + warp * 32;
    #pragma unroll
    for (int g = 0; g < 8; g++) {
        int row = base + g * 4 + r;
        float dot = 0.0f;
        #pragma unroll
        for (int k = 0; k < 4; k++) {
            float4 m = mb4[row * 32 + k * 8 + c];
            dot += q4[k].x * m.x + q4[k].y * m.y + q4[k].z * m.z + q4[k].w * m.w;
        }
        #pragma unroll
        for (int o = 1; o <= 4; o <<= 1) dot += __shfl_xor_sync(0xFFFFFFFF, dot, o);
        float d2 = y2q - 2.0f * dot + g_y2[row];
        #pragma unroll
        for (int rr = 0; rr < 4; rr++) {
            float v = __shfl_sync(0xFFFFFFFF, d2, rr * 8);
            if (lane == 0) {
                int row2 = base + g * 4 + rr;
                if (v < tv[KNEIGH - 1] || (v == tv[KNEIGH - 1] && row2 < ti9[KNEIGH - 1])) {
                    int pos = KNEIGH - 1;
                    while (pos > 0 && (v < tv[pos - 1] || (v == tv[pos - 1] && row2 < ti9[pos - 1]))) {
                        tv[pos] = tv[pos - 1]; ti9[pos] = ti9[pos - 1]; pos--;
                    }
                    tv[pos] = v; ti9[pos] = row2;
                }
            }
        }
    }
    if (lane == 0) {
        int off = b * NDNN + (blockIdx.x * 8 + warp) * KNEIGH;
        #pragma unroll
        for (int j = 0; j < KNEIGH; j++) { g_d9v[off + j] = tv[j]; g_d9i[off + j] = ti9[j]; }
    }
    __syncthreads();

    // ---- last block for image b does the final merge + softmax + out[b] ----
    __shared__ int s_last;
    if (threadIdx.x == 0) {
        __threadfence();
        s_last = atomicAdd(&g_done[b], 1);
    }
    __syncthreads();
    if (s_last != gridDim.x - 1) return;

    const int tid = threadIdx.x;
    __shared__ float hv[256]; __shared__ int hidx[256]; __shared__ int hthr[256];
    __shared__ int sel[KNEIGH]; __shared__ float dists[KNEIGH];

    float mv[KNEIGH]; int mi[KNEIGH];
    #pragma unroll
    for (int j = 0; j < KNEIGH; j++) { mv[j] = FLT_MAX; mi[j] = INT_MAX; }
    for (int m = tid; m < NDNN; m += 256) {
        float v = g_d9v[b * NDNN + m];
        int ix = g_d9i[b * NDNN + m];
        if (v < mv[KNEIGH - 1] || (v == mv[KNEIGH - 1] && ix < mi[KNEIGH - 1])) {
            int pos = KNEIGH - 1;
            while (pos > 0 && (v < mv[pos - 1] || (v == mv[pos - 1] && ix < mi[pos - 1]))) {
                mv[pos] = mv[pos - 1]; mi[pos] = mi[pos - 1]; pos--;
            }
            mv[pos] = v; mi[pos] = ix;
        }
    }
    int cur = 0;
    for (int it = 0; it < KNEIGH; it++) {
        hv[tid] = (cur < KNEIGH) ? mv[cur] : FLT_MAX;
        hidx[tid] = (cur < KNEIGH) ? mi[cur] : INT_MAX;
        hthr[tid] = tid;
        __syncthreads();
        for (int s = 128; s > 0; s >>= 1) {
            if (tid < s) {
                if (hv[tid + s] < hv[tid] ||
                    (hv[tid + s] == hv[tid] && hidx[tid + s] < hidx[tid])) {
                    hv[tid] = hv[tid + s]; hidx[tid] = hidx[tid + s]; hthr[tid] = hthr[tid + s];
                }
            }
            __syncthreads();
        }
        if (tid == 0) sel[it] = hidx[0];
        int win = hthr[0];
        __syncthreads();
        if (tid == win) cur++;
    }

    if (tid < KNEIGH) {
        const float* q = emb + (size_t)g_qrow[b] * DDIM;
        const float* m = mb + (size_t)sel[tid] * DDIM;
        float dot = 0.0f, q2 = 0.0f;
        #pragma unroll 4
        for (int d = 0; d < DDIM; d++) { dot += q[d] * m[d]; q2 += q[d] * q[d]; }
        float d2 = q2 - 2.0f * dot + g_y2[sel[tid]];
        dists[tid] = sqrtf(fmaxf(d2, 0.0f));
    }
    __syncthreads();
    if (tid == 0) {
        float mx = dists[0];
        for (int j = 1; j < KNEIGH; j++) mx = fmaxf(mx, dists[j]);
        float sum = 0.0f, e0 = 0.0f;
        for (int j = 0; j < KNEIGH; j++) {
            float e = expf(dists[j] - mx);
            if (j == 0) e0 = e;
            sum += e;
        }
        float d2m = ord2f((uint32_t)(g_nnkey[b] >> 32));
        float score = sqrtf(fmaxf(g_x2[g_qrow[b]] + d2m, 0.0f));
        out[b] = (1.0f - e0 / sum) * score;
    }
}

// ---------------- fused upsample + separable Gaussian blur (8-row bands) ----------------
__global__ void k_map(float* __restrict__ out) {
    char* smem = s_raw;
    float* pm = reinterpret_cast<float*>(smem + MAP_PM);
    float* gs = reinterpret_cast<float*>(smem + MAP_GS);
    float* up = reinterpret_cast<float*>(smem + MAP_UP);   // [40][224]
    float* vt = reinterpret_cast<float*>(smem + MAP_VT);   // [8][224]
    const int band = blockIdx.x, b = blockIdx.y;
    const int tid = threadIdx.x;
    const int r0 = band * MAP_BAND;

    for (int i = tid; i < PPB; i += 256) pm[i] = g_pscore[b * PPB + i];
    if (tid < KSIZE) gs[tid] = g_gauss[tid];
    __syncthreads();

    for (int i = tid; i < MAP_UPR * 224; i += 256) {
        int j = i / 224, V = i % 224;
        int U = r0 - KRAD + j;
        if (U < 0) U = -U;
        if (U > OUTSZ - 1) U = 2 * (OUTSZ - 1) - U;
        float su = ((float)U + 0.5f) * 0.125f - 0.5f;
        float sv = ((float)V + 0.5f) * 0.125f - 0.5f;
        int u0 = (int)floorf(su), v0 = (int)floorf(sv);
        float tu = su - (float)u0, tvv = sv - (float)v0;
        int u0c = min(max(u0, 0), WIO - 1), u1c = min(max(u0 + 1, 0), WIO - 1);
        int v0c = min(max(v0, 0), WIO - 1), v1c = min(max(v0 + 1, 0), WIO - 1);
        float v00 = pm[u0c * WIO + v0c], v01 = pm[u0c * WIO + v1c];
        float v10 = pm[u1c * WIO + v0c], v11 = pm[u1c * WIO + v1c];
        float top = v00 + tvv * (v01 - v00);
        float bot = v10 + tvv * (v11 - v10);
        up[i] = top + tu * (bot - top);
    }
    __syncthreads();

    for (int i = tid; i < MAP_BAND * 224; i += 256) {
        int du = i / 224, V = i % 224;
        float acc = 0.0f;
        #pragma unroll
        for (int k = 0; k < KSIZE; k++) acc += gs[k] * up[(du + k) * 224 + V];
        vt[i] = acc;
    }
    __syncthreads();

    for (int i = tid; i < MAP_BAND * 224; i += 256) {
        int du = i / 224, V = i % 224;
        float acc = 0.0f;
        #pragma unroll
        for (int k = 0; k < KSIZE; k++) {
            int jv = V - KRAD + k;
            if (jv < 0) jv = -jv;
            if (jv > OUTSZ - 1) jv = 2 * (OUTSZ - 1) - jv;
            acc += gs[k] * vt[du * 224 + jv];
        }
        out[BATCH + (b * OUTSZ + r0 + du) * OUTSZ + V] = acc;
    }
}

// ---------------- launcher ----------------
extern "C" void kernel_launch(void* const* d_in, const int* in_sizes, int n_in,
                              void* d_out, int out_size) {
    const float* emb = (const float*)d_in[0];
    const float* mb = (const float*)d_in[1];
    float* out = (float*)d_out;

    static bool attr_set = false;
    if (!attr_set) {
        cudaFuncSetAttribute(k_dist_mma, cudaFuncAttributeMaxDynamicSharedMemorySize, SMEM_TOTAL);
        cudaFuncSetAttribute(k_map, cudaFuncAttributeMaxDynamicSharedMemorySize, MAP_SMEM);
        attr_set = true;
    }

    k_prep<<<(MROWS + NROWS) / 32, 256>>>(emb, mb);

    dim3 gdist(NROWS / BNR, NSPLIT);
    k_dist_mma<<<gdist, 128, SMEM_TOTAL>>>();

    k_score<<<BATCH, 256>>>();

    dim3 gq(128, BATCH);
    k_qpart<<<gq, 256>>>(emb, mb);

    dim3 gd9(128, BATCH);
    k_dnn9<<<gd9, 256>>>(emb, mb, out);

    dim3 gmap(OUTSZ / MAP_BAND, BATCH);
    k_map<<<gmap, 256, MAP_SMEM>>>(out);
}

// round 17
// speedup vs baseline: 1.1044x; 1.0414x over previous
#include <cuda_runtime.h>
#include <cuda_bf16.h>
#include <math.h>
#include <float.h>
#include <limits.h>
#include <stdint.h>

// ---------------- problem constants (fixed shapes) ----------------
#define NROWS 6272      // embedding rows
#define MROWS 32768     // memory bank rows
#define DDIM  128
#define BATCH 8
#define PPB   784
#define WIO   28
#define OUTSZ 224
#define KNEIGH 9
#define KSIZE 33
#define KRAD  16

#define NSPLIT 9
#define BNR 128                 // emb rows per CTA
#define BMC 64                  // mb cols per tile step
#define NTILES (MROWS / BMC)    // 512
#define LDTB 272                // smem tile row stride bytes (136 bf16)
#define TILE_A (128 * LDTB)     // 34816
#define TILE_B (64 * LDTB)      // 17408

// k_dist smem byte offsets
#define OFF_A     0
#define OFF_B0    (OFF_A + TILE_A)
#define OFF_B1    (OFF_B0 + TILE_B)
#define OFF_Y2    (OFF_B1 + TILE_B)            // 2 x 64 floats (halved y2)
#define OFF_RED   (OFF_Y2 + 512)               // 128*2 floats
#define SMEM_TOTAL (OFF_RED + 1024)            // 71680 bytes -> 3 CTAs/SM

// k_map smem layout (8-row bands: 40 upsample rows + 8 vt rows)
#define MAP_BAND  8
#define MAP_UPR   (MAP_BAND + 2 * KRAD)        // 40
#define MAP_PM    0
#define MAP_GS    3136
#define MAP_UP    3280
#define MAP_VT    (MAP_UP + MAP_UPR*224*4)
#define MAP_SMEM  (MAP_VT + MAP_BAND*224*4)    // ~47 KB

#define NDNN 9216                              // per-image dnn top9 partials (128 blk * 8 warps * 9)

// ---------------- device scratch ----------------
__device__ float g_y2[MROWS];
__device__ float g_y2h[MROWS];
__device__ float g_x2[NROWS];
__device__ float g_pval[NSPLIT * NROWS];
__device__ float g_pscore[NROWS];
__device__ int   g_qrow[BATCH];
__device__ unsigned long long g_nnkey[BATCH]; // packed (ordered d2-q2 | idx)
__device__ int   g_done[BATCH];
__device__ float g_d9v[BATCH * NDNN];         // d^2 partials
__device__ int   g_d9i[BATCH * NDNN];
__device__ float g_gauss[KSIZE];
__device__ __nv_bfloat16 g_embh[NROWS * DDIM];
__device__ __nv_bfloat16 g_mbh[MROWS * DDIM];

// ---------------- small helpers ----------------
__device__ __forceinline__ uint32_t smem_u32(const void* p) {
    uint32_t a;
    asm("{ .reg .u64 t; cvta.to.shared.u64 t, %1; cvt.u32.u64 %0, t; }" : "=r"(a) : "l"(p));
    return a;
}
__device__ __forceinline__ void cp_async16(uint32_t dst, const void* src) {
    asm volatile("cp.async.cg.shared.global [%0], [%1], 16;" :: "r"(dst), "l"(src));
}
#define CP_COMMIT() asm volatile("cp.async.commit_group;" ::: "memory")
#define CP_WAIT0()  asm volatile("cp.async.wait_group 0;" ::: "memory")

__device__ __forceinline__ void ldm_x4(uint32_t addr, uint32_t& r0, uint32_t& r1,
                                       uint32_t& r2, uint32_t& r3) {
    asm volatile("ldmatrix.sync.aligned.m8n8.x4.shared.b16 {%0,%1,%2,%3}, [%4];"
                 : "=r"(r0), "=r"(r1), "=r"(r2), "=r"(r3) : "r"(addr));
}
__device__ __forceinline__ void mma16816(float* c, const uint32_t* a, const uint32_t* b) {
    asm volatile("mma.sync.aligned.m16n8k16.row.col.f32.bf16.bf16.f32 "
                 "{%0,%1,%2,%3}, {%4,%5,%6,%7}, {%8,%9}, {%0,%1,%2,%3};"
                 : "+f"(c[0]), "+f"(c[1]), "+f"(c[2]), "+f"(c[3])
                 : "r"(a[0]), "r"(a[1]), "r"(a[2]), "r"(a[3]), "r"(b[0]), "r"(b[1]));
}
__device__ __forceinline__ uint32_t f2ord(float f) {
    uint32_t u = __float_as_uint(f);
    return (u & 0x80000000u) ? ~u : (u | 0x80000000u);
}
__device__ __forceinline__ float ord2f(uint32_t u) {
    uint32_t b = (u & 0x80000000u) ? (u & 0x7FFFFFFFu) : ~u;
    return __uint_as_float(b);
}

// ---------------- k_prep: gauss + y2 + x2 + bf16 split ----------------
__global__ void k_prep(const float* __restrict__ emb, const float* __restrict__ mb) {
    if (blockIdx.x == 0 && threadIdx.x == 0) {
        float tmp[KSIZE]; float s = 0.0f;
        for (int i = 0; i < KSIZE; i++) {
            float x = (float)i - (float)(KSIZE - 1) * 0.5f;
            float t = x / 4.0f;
            tmp[i] = expf(-0.5f * t * t); s += tmp[i];
        }
        for (int i = 0; i < KSIZE; i++) g_gauss[i] = tmp[i] / s;
    }
    const int warp = threadIdx.x >> 5, lane = threadIdx.x & 31;
    const int r = lane >> 3, c = lane & 7;
    const int grow = blockIdx.x * 32 + warp * 4 + r;
    const float4* src4;
    uint2* dst2;
    int row;
    bool is_mb = (grow < MROWS);
    if (is_mb) { src4 = reinterpret_cast<const float4*>(mb); dst2 = reinterpret_cast<uint2*>(g_mbh); row = grow; }
    else       { src4 = reinterpret_cast<const float4*>(emb); dst2 = reinterpret_cast<uint2*>(g_embh); row = grow - MROWS; }

    float s = 0.0f;
    #pragma unroll
    for (int k = 0; k < 4; k++) {
        int idx = row * 32 + k * 8 + c;
        float4 v = src4[idx];
        s += v.x * v.x + v.y * v.y + v.z * v.z + v.w * v.w;
        __nv_bfloat162 h0, h1;
        h0.x = __float2bfloat16_rn(v.x); h0.y = __float2bfloat16_rn(v.y);
        h1.x = __float2bfloat16_rn(v.z); h1.y = __float2bfloat16_rn(v.w);
        uint2 p;
        p.x = *reinterpret_cast<uint32_t*>(&h0);
        p.y = *reinterpret_cast<uint32_t*>(&h1);
        dst2[idx] = p;
    }
    #pragma unroll
    for (int o = 1; o <= 4; o <<= 1) s += __shfl_xor_sync(0xFFFFFFFF, s, o);
    if (c == 0) {
        if (is_mb) { g_y2[row] = s; g_y2h[row] = 0.5f * s; }
        else       { g_x2[row] = s; }
    }
}

// ---------------- mma.sync fused distance GEMM (K=128, bf16-hi) + max ----------------
extern __shared__ char s_raw[];

__device__ __forceinline__ void load_tileA_async(uint32_t sm_dst,
                                                 const __nv_bfloat16* __restrict__ src,
                                                 int row0, int tid) {
    #pragma unroll
    for (int k = 0; k < 16; k++) {
        int i = k * 128 + tid;
        int r = i >> 4, c = i & 15;
        cp_async16(sm_dst + (uint32_t)(r * LDTB + c * 16),
                   (const char*)(src + (size_t)(row0 + r) * DDIM) + c * 16);
    }
}
__device__ __forceinline__ void load_tileB_async(uint32_t sm_dst,
                                                 const __nv_bfloat16* __restrict__ src,
                                                 int row0, int tid) {
    #pragma unroll
    for (int k = 0; k < 8; k++) {
        int i = k * 128 + tid;
        int r = i >> 4, c = i & 15;
        cp_async16(sm_dst + (uint32_t)(r * LDTB + c * 16),
                   (const char*)(src + (size_t)(row0 + r) * DDIM) + c * 16);
    }
}

__global__ void __launch_bounds__(128, 3) k_dist_mma() {
    char* smem = s_raw;
    const uint32_t sbase = smem_u32(smem);
    const int tid = threadIdx.x;
    const int wid = tid >> 5;
    const int lane = tid & 31;
    const int wm = wid & 1;
    const int wn = wid >> 1;
    const int rowBase = blockIdx.x * BNR;

    const int tile0 = (blockIdx.y * NTILES) / NSPLIT;
    const int tile1 = ((blockIdx.y + 1) * NTILES) / NSPLIT;

    const uint32_t A = sbase + OFF_A;
    const uint32_t B[2] = { sbase + OFF_B0, sbase + OFF_B1 };
    float* y2s = reinterpret_cast<float*>(smem + OFF_Y2);

    const int a_row = lane & 15;
    const int a_koff = (lane >> 4) << 3;
    const uint32_t aOff = (uint32_t)((wm * 64 + a_row) * LDTB + a_koff * 2);
    const int b_n = (lane & 7) + ((lane >> 4) << 3);
    const int b_koff = ((lane >> 3) & 1) << 3;
    const uint32_t bOff = (uint32_t)((wn * 32 + b_n) * LDTB + b_koff * 2);

    load_tileA_async(A, g_embh, rowBase, tid);
    load_tileB_async(B[0], g_mbh, tile0 * BMC, tid);
    if (tid < 16)
        cp_async16(sbase + OFF_Y2 + tid * 16, (const char*)(g_y2h + tile0 * BMC) + tid * 16);
    CP_COMMIT();
    CP_WAIT0();
    __syncthreads();

    float bestV[8];
    #pragma unroll
    for (int i = 0; i < 8; i++) bestV[i] = -FLT_MAX;

    for (int t = tile0; t < tile1; t++) {
        const int buf = (t - tile0) & 1;

        if (t + 1 < tile1) {
            const int nb = buf ^ 1;
            load_tileB_async(B[nb], g_mbh, (t + 1) * BMC, tid);
            if (tid < 16)
                cp_async16(sbase + OFF_Y2 + (uint32_t)(nb * 256 + tid * 16),
                           (const char*)(g_y2h + (size_t)(t + 1) * BMC) + tid * 16);
            CP_COMMIT();
        }

        float acc[4][4][4];
        #pragma unroll
        for (int mf = 0; mf < 4; mf++)
            #pragma unroll
            for (int nf = 0; nf < 4; nf++)
                #pragma unroll
                for (int r = 0; r < 4; r++) acc[mf][nf][r] = 0.0f;

        const uint32_t aB = A + aOff;
        const uint32_t bB = B[buf] + bOff;
        #pragma unroll
        for (int kc = 0; kc < 8; kc++) {
            const uint32_t kByte = (uint32_t)(kc << 5);
            uint32_t af[4][4];
            #pragma unroll
            for (int mf = 0; mf < 4; mf++)
                ldm_x4(aB + (uint32_t)(mf * 16 * LDTB) + kByte,
                       af[mf][0], af[mf][1], af[mf][2], af[mf][3]);
            uint32_t bf[4][2];
            #pragma unroll
            for (int q = 0; q < 2; q++) {
                uint32_t r0, r1, r2, r3;
                ldm_x4(bB + (uint32_t)(q * 16 * LDTB) + kByte, r0, r1, r2, r3);
                bf[q * 2][0] = r0; bf[q * 2][1] = r1;
                bf[q * 2 + 1][0] = r2; bf[q * 2 + 1][1] = r3;
            }
            #pragma unroll
            for (int mf = 0; mf < 4; mf++)
                #pragma unroll
                for (int nf = 0; nf < 4; nf++)
                    mma16816(acc[mf][nf], af[mf], bf[nf]);
        }

        {
            const float2* hy2 = reinterpret_cast<const float2*>(y2s + buf * 64);
            float2 hv[4];
            #pragma unroll
            for (int nf = 0; nf < 4; nf++)
                hv[nf] = hy2[(wn * 32 + nf * 8 + (lane & 3) * 2) >> 1];
            #pragma unroll
            for (int mf = 0; mf < 4; mf++) {
                #pragma unroll
                for (int h = 0; h < 2; h++) {
                    const int slot = mf * 2 + h;
                    float bv = bestV[slot];
                    #pragma unroll
                    for (int nf = 0; nf < 4; nf++) {
                        float s0 = acc[mf][nf][h * 2] - hv[nf].x;
                        float s1 = acc[mf][nf][h * 2 + 1] - hv[nf].y;
                        bv = fmaxf(bv, fmaxf(s0, s1));
                    }
                    bestV[slot] = bv;
                }
            }
        }

        if (t + 1 < tile1) CP_WAIT0();
        __syncthreads();
    }

    float* redV = reinterpret_cast<float*>(smem + OFF_RED);
    #pragma unroll
    for (int slot = 0; slot < 8; slot++) {
        float v = bestV[slot];
        v = fmaxf(v, __shfl_xor_sync(0xFFFFFFFF, v, 1));
        v = fmaxf(v, __shfl_xor_sync(0xFFFFFFFF, v, 2));
        if ((lane & 3) == 0) {
            int mf = slot >> 1, h = slot & 1;
            int row = wm * 64 + mf * 16 + (lane >> 2) + h * 8;
            redV[row * 2 + wn] = v;
        }
    }
    __syncthreads();
    if (tid < BNR) {
        float bv = fmaxf(redV[tid * 2], redV[tid * 2 + 1]);
        g_pval[blockIdx.y * NROWS + rowBase + tid] = bv;
    }
}

// ---------------- fused: patch scores + per-image argmax (+reset keys) ----------------
__global__ void k_score() {
    int b = blockIdx.x, tid = threadIdx.x;
    __shared__ float sv[256]; __shared__ int si[256];
    if (tid == 0) { g_nnkey[b] = 0xFFFFFFFFFFFFFFFFull; g_done[b] = 0; }
    float bmax = -FLT_MAX; int bi = INT_MAX;
    for (int p = tid; p < PPB; p += 256) {
        int row = b * PPB + p;
        float bv = -FLT_MAX;
        #pragma unroll
        for (int s = 0; s < NSPLIT; s++) bv = fmaxf(bv, g_pval[s * NROWS + row]);
        float d2 = g_x2[row] - 2.0f * bv;
        float sc = sqrtf(fmaxf(d2, 0.0f));
        g_pscore[row] = sc;
        if (sc > bmax || (sc == bmax && p < bi)) { bmax = sc; bi = p; }
    }
    sv[tid] = bmax; si[tid] = bi;
    __syncthreads();
    for (int s = 128; s > 0; s >>= 1) {
        if (tid < s) {
            if (sv[tid + s] > sv[tid] || (sv[tid + s] == sv[tid] && si[tid + s] < si[tid])) {
                sv[tid] = sv[tid + s]; si[tid] = si[tid + s];
            }
        }
        __syncthreads();
    }
    if (tid == 0) g_qrow[b] = b * PPB + si[0];
}

// ---------------- exact fp32 argmin over mb, row-pair MLP, atomic-merged ----------------
// grid (128, 8), block 256 = 8 warps x 32 rows
__global__ void k_qpart(const float* __restrict__ emb, const float* __restrict__ mb) {
    const int b = blockIdx.y;
    const int warp = threadIdx.x >> 5, lane = threadIdx.x & 31;
    const int r = lane >> 3, c = lane & 7;
    const float4* mb4 = reinterpret_cast<const float4*>(mb);
    const float4* q4p = reinterpret_cast<const float4*>(emb + (size_t)g_qrow[b] * DDIM);

    float4 q4[4];
    #pragma unroll
    for (int k = 0; k < 4; k++) q4[k] = q4p[k * 8 + c];

    float bv = FLT_MAX; int bi = INT_MAX;
    const int base = blockIdx.x * 256 + warp * 32;
    #pragma unroll
    for (int g = 0; g < 8; g += 2) {
        int row0 = base + g * 4 + r;
        int row1 = row0 + 4;
        float4 m0[4], m1[4];
        #pragma unroll
        for (int k = 0; k < 4; k++) m0[k] = mb4[row0 * 32 + k * 8 + c];
        #pragma unroll
        for (int k = 0; k < 4; k++) m1[k] = mb4[row1 * 32 + k * 8 + c];
        float d0 = 0.0f, d1 = 0.0f;
        #pragma unroll
        for (int k = 0; k < 4; k++) {
            d0 += q4[k].x * m0[k].x + q4[k].y * m0[k].y + q4[k].z * m0[k].z + q4[k].w * m0[k].w;
            d1 += q4[k].x * m1[k].x + q4[k].y * m1[k].y + q4[k].z * m1[k].z + q4[k].w * m1[k].w;
        }
        #pragma unroll
        for (int o = 1; o <= 4; o <<= 1) {
            d0 += __shfl_xor_sync(0xFFFFFFFF, d0, o);
            d1 += __shfl_xor_sync(0xFFFFFFFF, d1, o);
        }
        float e0 = g_y2[row0] - 2.0f * d0;   // +q^2 constant: argmin-invariant
        float e1 = g_y2[row1] - 2.0f * d1;
        if (e0 < bv) { bv = e0; bi = row0; }
        if (e1 < bv) { bv = e1; bi = row1; }
    }
    #pragma unroll
    for (int o = 8; o <= 16; o <<= 1) {
        float ov = __shfl_xor_sync(0xFFFFFFFF, bv, o);
        int oi = __shfl_xor_sync(0xFFFFFFFF, bi, o);
        if (ov < bv || (ov == bv && oi < bi)) { bv = ov; bi = oi; }
    }
    __shared__ float sv[8]; __shared__ int si[8];
    if (lane == 0) { sv[warp] = bv; si[warp] = bi; }
    __syncthreads();
    if (threadIdx.x == 0) {
        float v = sv[0]; int ix = si[0];
        for (int w = 1; w < 8; w++)
            if (sv[w] < v || (sv[w] == v && si[w] < ix)) { v = sv[w]; ix = si[w]; }
        unsigned long long key = ((unsigned long long)f2ord(v) << 32) | (unsigned)ix;
        atomicMin(&g_nnkey[b], key);
    }
}

// ---------------- dnn d^2 top-9 partials + last-block final merge ----------------
// grid (128, 8), block 256 = 8 warps x 32 rows
__global__ void k_dnn9(const float* __restrict__ emb, const float* __restrict__ mb,
                       float* __restrict__ out) {
    const int b = blockIdx.y;
    const int warp = threadIdx.x >> 5, lane = threadIdx.x & 31;
    const int r = lane >> 3, c = lane & 7;
    const int nn = (int)(g_nnkey[b] & 0xFFFFFFFFull);
    const float4* mb4 = reinterpret_cast<const float4*>(mb);
    const float4* q4p = reinterpret_cast<const float4*>(mb + (size_t)nn * DDIM);
    const float y2q = g_y2[nn];

    float4 q4[4];
    #pragma unroll
    for (int k = 0; k < 4; k++) q4[k] = q4p[k * 8 + c];

    float tv[KNEIGH]; int ti9[KNEIGH];
    #pragma unroll
    for (int j = 0; j < KNEIGH; j++) { tv[j] = FLT_MAX; ti9[j] = INT_MAX; }

    const int base = blockIdx.x * 256 + warp * 32;
    #pragma unroll
    for (int g = 0; g < 8; g += 2) {
        int row0 = base + g * 4 + r;
        int row1 = row0 + 4;
        float4 m0[4], m1[4];
        #pragma unroll
        for (int k = 0; k < 4; k++) m0[k] = mb4[row0 * 32 + k * 8 + c];
        #pragma unroll
        for (int k = 0; k < 4; k++) m1[k] = mb4[row1 * 32 + k * 8 + c];
        float d0 = 0.0f, d1 = 0.0f;
        #pragma unroll
        for (int k = 0; k < 4; k++) {
            d0 += q4[k].x * m0[k].x + q4[k].y * m0[k].y + q4[k].z * m0[k].z + q4[k].w * m0[k].w;
            d1 += q4[k].x * m1[k].x + q4[k].y * m1[k].y + q4[k].z * m1[k].z + q4[k].w * m1[k].w;
        }
        #pragma unroll
        for (int o = 1; o <= 4; o <<= 1) {
            d0 += __shfl_xor_sync(0xFFFFFFFF, d0, o);
            d1 += __shfl_xor_sync(0xFFFFFFFF, d1, o);
        }
        float e0 = y2q - 2.0f * d0 + g_y2[row0];
        float e1 = y2q - 2.0f * d1 + g_y2[row1];
        #pragma unroll
        for (int rr = 0; rr < 4; rr++) {
            float v0 = __shfl_sync(0xFFFFFFFF, e0, rr * 8);
            float v1 = __shfl_sync(0xFFFFFFFF, e1, rr * 8);
            if (lane == 0) {
                int rowa = base + g * 4 + rr;
                int rowb = rowa + 4;
                if (v0 < tv[KNEIGH - 1] || (v0 == tv[KNEIGH - 1] && rowa < ti9[KNEIGH - 1])) {
                    int pos = KNEIGH - 1;
                    while (pos > 0 && (v0 < tv[pos - 1] || (v0 == tv[pos - 1] && rowa < ti9[pos - 1]))) {
                        tv[pos] = tv[pos - 1]; ti9[pos] = ti9[pos - 1]; pos--;
                    }
                    tv[pos] = v0; ti9[pos] = rowa;
                }
                if (v1 < tv[KNEIGH - 1] || (v1 == tv[KNEIGH - 1] && rowb < ti9[KNEIGH - 1])) {
                    int pos = KNEIGH - 1;
                    while (pos > 0 && (v1 < tv[pos - 1] || (v1 == tv[pos - 1] && rowb < ti9[pos - 1]))) {
                        tv[pos] = tv[pos - 1]; ti9[pos] = ti9[pos - 1]; pos--;
                    }
                    tv[pos] = v1; ti9[pos] = rowb;
                }
            }
        }
    }
    if (lane == 0) {
        int off = b * NDNN + (blockIdx.x * 8 + warp) * KNEIGH;
        #pragma unroll
        for (int j = 0; j < KNEIGH; j++) { g_d9v[off + j] = tv[j]; g_d9i[off + j] = ti9[j]; }
    }
    __syncthreads();

    // ---- last block for image b does the final merge + softmax + out[b] ----
    __shared__ int s_last;
    if (threadIdx.x == 0) {
        __threadfence();
        s_last = atomicAdd(&g_done[b], 1);
    }
    __syncthreads();
    if (s_last != gridDim.x - 1) return;

    const int tid = threadIdx.x;
    __shared__ float hv[256]; __shared__ int hidx[256]; __shared__ int hthr[256];
    __shared__ int sel[KNEIGH]; __shared__ float dists[KNEIGH];

    float mv[KNEIGH]; int mi[KNEIGH];
    #pragma unroll
    for (int j = 0; j < KNEIGH; j++) { mv[j] = FLT_MAX; mi[j] = INT_MAX; }
    for (int m = tid; m < NDNN; m += 256) {
        float v = g_d9v[b * NDNN + m];
        int ix = g_d9i[b * NDNN + m];
        if (v < mv[KNEIGH - 1] || (v == mv[KNEIGH - 1] && ix < mi[KNEIGH - 1])) {
            int pos = KNEIGH - 1;
            while (pos > 0 && (v < mv[pos - 1] || (v == mv[pos - 1] && ix < mi[pos - 1]))) {
                mv[pos] = mv[pos - 1]; mi[pos] = mi[pos - 1]; pos--;
            }
            mv[pos] = v; mi[pos] = ix;
        }
    }
    int cur = 0;
    for (int it = 0; it < KNEIGH; it++) {
        hv[tid] = (cur < KNEIGH) ? mv[cur] : FLT_MAX;
        hidx[tid] = (cur < KNEIGH) ? mi[cur] : INT_MAX;
        hthr[tid] = tid;
        __syncthreads();
        for (int s = 128; s > 0; s >>= 1) {
            if (tid < s) {
                if (hv[tid + s] < hv[tid] ||
                    (hv[tid + s] == hv[tid] && hidx[tid + s] < hidx[tid])) {
                    hv[tid] = hv[tid + s]; hidx[tid] = hidx[tid + s]; hthr[tid] = hthr[tid + s];
                }
            }
            __syncthreads();
        }
        if (tid == 0) sel[it] = hidx[0];
        int win = hthr[0];
        __syncthreads();
        if (tid == win) cur++;
    }

    if (tid < KNEIGH) {
        const float* q = emb + (size_t)g_qrow[b] * DDIM;
        const float* m = mb + (size_t)sel[tid] * DDIM;
        float dot = 0.0f, q2 = 0.0f;
        #pragma unroll 4
        for (int d = 0; d < DDIM; d++) { dot += q[d] * m[d]; q2 += q[d] * q[d]; }
        float d2 = q2 - 2.0f * dot + g_y2[sel[tid]];
        dists[tid] = sqrtf(fmaxf(d2, 0.0f));
    }
    __syncthreads();
    if (tid == 0) {
        float mx = dists[0];
        for (int j = 1; j < KNEIGH; j++) mx = fmaxf(mx, dists[j]);
        float sum = 0.0f, e0 = 0.0f;
        for (int j = 0; j < KNEIGH; j++) {
            float e = expf(dists[j] - mx);
            if (j == 0) e0 = e;
            sum += e;
        }
        float d2m = ord2f((uint32_t)(g_nnkey[b] >> 32));
        float score = sqrtf(fmaxf(g_x2[g_qrow[b]] + d2m, 0.0f));
        out[b] = (1.0f - e0 / sum) * score;
    }
}

// ---------------- fused upsample + separable Gaussian blur (8-row bands) ----------------
__global__ void k_map(float* __restrict__ out) {
    char* smem = s_raw;
    float* pm = reinterpret_cast<float*>(smem + MAP_PM);
    float* gs = reinterpret_cast<float*>(smem + MAP_GS);
    float* up = reinterpret_cast<float*>(smem + MAP_UP);   // [40][224]
    float* vt = reinterpret_cast<float*>(smem + MAP_VT);   // [8][224]
    const int band = blockIdx.x, b = blockIdx.y;
    const int tid = threadIdx.x;
    const int r0 = band * MAP_BAND;

    for (int i = tid; i < PPB; i += 256) pm[i] = g_pscore[b * PPB + i];
    if (tid < KSIZE) gs[tid] = g_gauss[tid];
    __syncthreads();

    for (int i = tid; i < MAP_UPR * 224; i += 256) {
        int j = i / 224, V = i % 224;
        int U = r0 - KRAD + j;
        if (U < 0) U = -U;
        if (U > OUTSZ - 1) U = 2 * (OUTSZ - 1) - U;
        float su = ((float)U + 0.5f) * 0.125f - 0.5f;
        float sv = ((float)V + 0.5f) * 0.125f - 0.5f;
        int u0 = (int)floorf(su), v0 = (int)floorf(sv);
        float tu = su - (float)u0, tvv = sv - (float)v0;
        int u0c = min(max(u0, 0), WIO - 1), u1c = min(max(u0 + 1, 0), WIO - 1);
        int v0c = min(max(v0, 0), WIO - 1), v1c = min(max(v0 + 1, 0), WIO - 1);
        float v00 = pm[u0c * WIO + v0c], v01 = pm[u0c * WIO + v1c];
        float v10 = pm[u1c * WIO + v0c], v11 = pm[u1c * WIO + v1c];
        float top = v00 + tvv * (v01 - v00);
        float bot = v10 + tvv * (v11 - v10);
        up[i] = top + tu * (bot - top);
    }
    __syncthreads();

    for (int i = tid; i < MAP_BAND * 224; i += 256) {
        int du = i / 224, V = i % 224;
        float acc = 0.0f;
        #pragma unroll
        for (int k = 0; k < KSIZE; k++) acc += gs[k] * up[(du + k) * 224 + V];
        vt[i] = acc;
    }
    __syncthreads();

    for (int i = tid; i < MAP_BAND * 224; i += 256) {
        int du = i / 224, V = i % 224;
        float acc = 0.0f;
        #pragma unroll
        for (int k = 0; k < KSIZE; k++) {
            int jv = V - KRAD + k;
            if (jv < 0) jv = -jv;
            if (jv > OUTSZ - 1) jv = 2 * (OUTSZ - 1) - jv;
            acc += gs[k] * vt[du * 224 + jv];
        }
        out[BATCH + (b * OUTSZ + r0 + du) * OUTSZ + V] = acc;
    }
}

// ---------------- launcher ----------------
extern "C" void kernel_launch(void* const* d_in, const int* in_sizes, int n_in,
                              void* d_out, int out_size) {
    const float* emb = (const float*)d_in[0];
    const float* mb = (const float*)d_in[1];
    float* out = (float*)d_out;

    static bool attr_set = false;
    if (!attr_set) {
        cudaFuncSetAttribute(k_dist_mma, cudaFuncAttributeMaxDynamicSharedMemorySize, SMEM_TOTAL);
        cudaFuncSetAttribute(k_map, cudaFuncAttributeMaxDynamicSharedMemorySize, MAP_SMEM);
        attr_set = true;
    }

    k_prep<<<(MROWS + NROWS) / 32, 256>>>(emb, mb);

    dim3 gdist(NROWS / BNR, NSPLIT);
    k_dist_mma<<<gdist, 128, SMEM_TOTAL>>>();

    k_score<<<BATCH, 256>>>();

    dim3 gq(128, BATCH);
    k_qpart<<<gq, 256>>>(emb, mb);

    dim3 gd9(128, BATCH);
    k_dnn9<<<gd9, 256>>>(emb, mb, out);

    dim3 gmap(OUTSZ / MAP_BAND, BATCH);
    k_map<<<gmap, 256, MAP_SMEM>>>(out);
}